// round 11
// baseline (speedup 1.0000x reference)
#include <cuda_runtime.h>
#include <math_constants.h>
#include <stdint.h>

#define MAXN 100000
#define MAXE 1600000
#define F 128
#define F4 32
#define NCLS 40
#define NSB  128   // max scan blocks (MAXN/1024+1 = 99)

// ---------------- device scratch ----------------
__device__ int   g_is64;
__device__ int   g_src[MAXE];
__device__ int   g_dst[MAXE];
__device__ int2  g_perm[MAXE];     // .x = src node, .y = edge_attr bits
__device__ int   g_counts[MAXN + 1];
__device__ int   g_offsets[MAXN + 1];
__device__ int   g_cursor[MAXN];
__device__ int   g_bsum[NSB];
__device__ int   g_boff[NSB];
__device__ float g_buf_b[(size_t)MAXN * F];

// ---------------- dtype detection ----------------
__global__ void detect_kernel(const unsigned int* __restrict__ ei) {
    __shared__ int any_nonzero;
    if (threadIdx.x == 0) any_nonzero = 0;
    __syncthreads();
    for (int i = threadIdx.x; i < 1024; i += blockDim.x) {
        if (ei[2 * i + 1] != 0u) any_nonzero = 1;
    }
    __syncthreads();
    if (threadIdx.x == 0) g_is64 = (any_nonzero == 0) ? 1 : 0;
}

__global__ void zero_counts_kernel(int n) {
    int i = blockIdx.x * blockDim.x + threadIdx.x;
    if (i <= n) g_counts[i] = 0;
}

// extract + histogram in one pass over E
__global__ void extract_hist_kernel(const void* __restrict__ ei, int E) {
    int e = blockIdx.x * blockDim.x + threadIdx.x;
    if (e >= E) return;
    int s, d;
    if (g_is64) {
        const long long* p = (const long long*)ei;
        s = (int)p[e];
        d = (int)p[(size_t)E + e];
    } else {
        const int* p = (const int*)ei;
        s = p[e];
        d = p[E + e];
    }
    g_src[e] = s;
    g_dst[e] = d;
    atomicAdd(&g_counts[d], 1);
}

// ---------------- 3-phase coalesced scan over counts[0..n] ----------------
__global__ void __launch_bounds__(1024) scan_sums_kernel(int n) {
    __shared__ int wsum[32];
    int i = blockIdx.x * 1024 + threadIdx.x;
    int v = (i <= n) ? g_counts[i] : 0;
    #pragma unroll
    for (int o = 16; o > 0; o >>= 1) v += __shfl_xor_sync(0xffffffffu, v, o);
    if ((threadIdx.x & 31) == 0) wsum[threadIdx.x >> 5] = v;
    __syncthreads();
    if (threadIdx.x < 32) {
        int s = wsum[threadIdx.x];
        #pragma unroll
        for (int o = 16; o > 0; o >>= 1) s += __shfl_xor_sync(0xffffffffu, s, o);
        if (threadIdx.x == 0) g_bsum[blockIdx.x] = s;
    }
}

__global__ void scan_blocks_kernel(int nb) {
    __shared__ int sm[NSB];
    int t = threadIdx.x;
    int v = (t < nb) ? g_bsum[t] : 0;
    sm[t] = v;
    __syncthreads();
    #pragma unroll
    for (int o = 1; o < NSB; o <<= 1) {
        int y = (t >= o) ? sm[t - o] : 0;
        __syncthreads();
        sm[t] += y;
        __syncthreads();
    }
    if (t < nb) g_boff[t] = sm[t] - v;   // exclusive
}

__global__ void __launch_bounds__(1024) scan_apply_kernel(int n) {
    __shared__ int wsum[32];
    int lane = threadIdx.x & 31;
    int wid  = threadIdx.x >> 5;
    int i = blockIdx.x * 1024 + threadIdx.x;
    int v = (i <= n) ? g_counts[i] : 0;
    int x = v;
    #pragma unroll
    for (int o = 1; o < 32; o <<= 1) {
        int y = __shfl_up_sync(0xffffffffu, x, o);
        if (lane >= o) x += y;
    }
    if (lane == 31) wsum[wid] = x;
    __syncthreads();
    if (wid == 0) {
        int s = wsum[lane];
        #pragma unroll
        for (int o = 1; o < 32; o <<= 1) {
            int y = __shfl_up_sync(0xffffffffu, s, o);
            if (lane >= o) s += y;
        }
        wsum[lane] = s;
    }
    __syncthreads();
    int excl = x - v + (wid > 0 ? wsum[wid - 1] : 0) + g_boff[blockIdx.x];
    if (i <= n) {
        g_offsets[i] = excl;
        if (i < n) g_cursor[i] = excl;
    }
}

__global__ void scatter_kernel(const float* __restrict__ edge_attr, int E) {
    int e = blockIdx.x * blockDim.x + threadIdx.x;
    if (e >= E) return;
    int d = g_dst[e];
    int pos = atomicAdd(&g_cursor[d], 1);
    g_perm[pos] = make_int2(g_src[e], __float_as_int(edge_attr[e]));
}

// ---------------- tf32 helpers ----------------
__device__ __forceinline__ uint32_t f2tf32(float x) {
    uint32_t r;
    asm("cvt.rna.tf32.f32 %0, %1;" : "=r"(r) : "f"(x));
    return r;
}
__device__ __forceinline__ void split_tf32(float x, uint32_t& hi, uint32_t& lo) {
    hi = f2tf32(x);
    lo = f2tf32(x - __uint_as_float(hi));
}
__device__ __forceinline__ void mma_tf32(float* d, const uint32_t* a, const uint32_t* b) {
    asm volatile(
        "mma.sync.aligned.m16n8k8.row.col.f32.tf32.tf32.f32 "
        "{%0,%1,%2,%3}, {%4,%5,%6,%7}, {%8,%9}, {%0,%1,%2,%3};"
        : "+f"(d[0]), "+f"(d[1]), "+f"(d[2]), "+f"(d[3])
        : "r"(a[0]), "r"(a[1]), "r"(a[2]), "r"(a[3]), "r"(b[0]), "r"(b[1]));
}

// ---------------- fused GINE conv: agg (smem) + MLP (+ optional classifier) ----------------
#define TM   64
#define SLDK 132   // As[m][k] row stride (conflict-free)
#define SLDB 136   // Bs[k][n] row stride
#define LSLD 44
#define SMEM_MLP ((TM * SLDK + 128 * SLDB) * 4)

template <bool FUSE_CLS>
__global__ void __launch_bounds__(256, 2) gine_kernel(
    const float4* __restrict__ xin,
    const float* __restrict__ We, const float* __restrict__ be,
    const float* __restrict__ eps_p,
    const float* __restrict__ W1, const float* __restrict__ b1,
    const float* __restrict__ W2, const float* __restrict__ b2,
    float* __restrict__ Out, int n,
    const float* __restrict__ Wl, const float* __restrict__ bl,
    float* __restrict__ cls_out)
{
    extern __shared__ float sm[];
    float* As = sm;                // [TM m][128 k] row-major
    float* Bs = sm + TM * SLDK;    // [128 k][128 n]

    const int t    = threadIdx.x;
    const int lane = t & 31;
    const int wid  = t >> 5;
    const int wm   = wid & 1;
    const int wn   = wid >> 1;
    const int m0   = blockIdx.x * TM;
    const int lq   = lane & 3;
    const int lg   = lane >> 2;

    // ---- phase 0: aggregation directly into As ----
    // each warp aggregates 8 nodes (warp-per-node CSR loop, lane covers 4 feats)
    {
        float4 w   = ((const float4*)We)[lane];
        float4 bbv = ((const float4*)be)[lane];
        float  epv = 1.f + __ldg(eps_p);
        #pragma unroll 1
        for (int i = 0; i < 8; i++) {
            int ml = wid * 8 + i;
            int m  = m0 + ml;
            float4 acc = make_float4(0.f, 0.f, 0.f, 0.f);
            if (m < n) {
                int beg = g_offsets[m];
                int end = g_offsets[m + 1];
                int p = beg;
                for (; p + 3 < end; p += 4) {
                    int2 pe0 = g_perm[p];
                    int2 pe1 = g_perm[p + 1];
                    int2 pe2 = g_perm[p + 2];
                    int2 pe3 = g_perm[p + 3];
                    float4 x0 = __ldg(&xin[(size_t)pe0.x * F4 + lane]);
                    float4 x1 = __ldg(&xin[(size_t)pe1.x * F4 + lane]);
                    float4 x2 = __ldg(&xin[(size_t)pe2.x * F4 + lane]);
                    float4 x3 = __ldg(&xin[(size_t)pe3.x * F4 + lane]);
                    float e0 = __int_as_float(pe0.y);
                    float e1 = __int_as_float(pe1.y);
                    float e2 = __int_as_float(pe2.y);
                    float e3 = __int_as_float(pe3.y);
                    acc.x += fmaxf(fmaf(e0, w.x, x0.x) + bbv.x, 0.f);
                    acc.y += fmaxf(fmaf(e0, w.y, x0.y) + bbv.y, 0.f);
                    acc.z += fmaxf(fmaf(e0, w.z, x0.z) + bbv.z, 0.f);
                    acc.w += fmaxf(fmaf(e0, w.w, x0.w) + bbv.w, 0.f);
                    acc.x += fmaxf(fmaf(e1, w.x, x1.x) + bbv.x, 0.f);
                    acc.y += fmaxf(fmaf(e1, w.y, x1.y) + bbv.y, 0.f);
                    acc.z += fmaxf(fmaf(e1, w.z, x1.z) + bbv.z, 0.f);
                    acc.w += fmaxf(fmaf(e1, w.w, x1.w) + bbv.w, 0.f);
                    acc.x += fmaxf(fmaf(e2, w.x, x2.x) + bbv.x, 0.f);
                    acc.y += fmaxf(fmaf(e2, w.y, x2.y) + bbv.y, 0.f);
                    acc.z += fmaxf(fmaf(e2, w.z, x2.z) + bbv.z, 0.f);
                    acc.w += fmaxf(fmaf(e2, w.w, x2.w) + bbv.w, 0.f);
                    acc.x += fmaxf(fmaf(e3, w.x, x3.x) + bbv.x, 0.f);
                    acc.y += fmaxf(fmaf(e3, w.y, x3.y) + bbv.y, 0.f);
                    acc.z += fmaxf(fmaf(e3, w.z, x3.z) + bbv.z, 0.f);
                    acc.w += fmaxf(fmaf(e3, w.w, x3.w) + bbv.w, 0.f);
                }
                for (; p < end; p++) {
                    int2 pe = g_perm[p];
                    float4 xj = __ldg(&xin[(size_t)pe.x * F4 + lane]);
                    float ea = __int_as_float(pe.y);
                    acc.x += fmaxf(fmaf(ea, w.x, xj.x) + bbv.x, 0.f);
                    acc.y += fmaxf(fmaf(ea, w.y, xj.y) + bbv.y, 0.f);
                    acc.z += fmaxf(fmaf(ea, w.z, xj.z) + bbv.z, 0.f);
                    acc.w += fmaxf(fmaf(ea, w.w, xj.w) + bbv.w, 0.f);
                }
                float4 xi = __ldg(&xin[(size_t)m * F4 + lane]);
                acc.x = fmaf(epv, xi.x, acc.x);
                acc.y = fmaf(epv, xi.y, acc.y);
                acc.z = fmaf(epv, xi.z, acc.z);
                acc.w = fmaf(epv, xi.w, acc.w);
            }
            *(float4*)(As + ml * SLDK + lane * 4) = acc;
        }
    }
    // Load W1 into Bs
    #pragma unroll
    for (int r = 0; r < 16; r++) {
        int idx = t + r * 256;
        int k   = idx >> 5;
        int c4  = (idx & 31) * 4;
        *(float4*)(Bs + k * SLDB + c4) = *(const float4*)(W1 + k * F + c4);
    }
    __syncthreads();

    float acc[2][4][4];
    #pragma unroll
    for (int i = 0; i < 2; i++)
        #pragma unroll
        for (int j = 0; j < 4; j++)
            #pragma unroll
            for (int c = 0; c < 4; c++) acc[i][j][c] = 0.f;

    // ---- stage 1: T = Agg @ W1 ----
    #pragma unroll 4
    for (int ks = 0; ks < 128; ks += 8) {
        uint32_t ahi[2][4], alo[2][4], bhi[4][2], blo[4][2];
        #pragma unroll
        for (int mt = 0; mt < 2; mt++) {
            int mb = wm * 32 + mt * 16 + lg;
            const float* ap = As + mb * SLDK + ks + lq;
            split_tf32(ap[0],            ahi[mt][0], alo[mt][0]);
            split_tf32(ap[8 * SLDK],     ahi[mt][1], alo[mt][1]);
            split_tf32(ap[4],            ahi[mt][2], alo[mt][2]);
            split_tf32(ap[8 * SLDK + 4], ahi[mt][3], alo[mt][3]);
        }
        #pragma unroll
        for (int nt = 0; nt < 4; nt++) {
            int nb = wn * 32 + nt * 8 + lg;
            const float* bp = Bs + (ks + lq) * SLDB + nb;
            split_tf32(bp[0],        bhi[nt][0], blo[nt][0]);
            split_tf32(bp[4 * SLDB], bhi[nt][1], blo[nt][1]);
        }
        #pragma unroll
        for (int mt = 0; mt < 2; mt++)
            #pragma unroll
            for (int nt = 0; nt < 4; nt++) {
                mma_tf32(acc[mt][nt], ahi[mt], bhi[nt]);
                mma_tf32(acc[mt][nt], ahi[mt], blo[nt]);
                mma_tf32(acc[mt][nt], alo[mt], bhi[nt]);
            }
    }
    __syncthreads();

    // epilogue 1: T = relu(acc + b1) stored into As[m][hidden]
    #pragma unroll
    for (int mt = 0; mt < 2; mt++) {
        int r0 = wm * 32 + mt * 16 + lg;
        #pragma unroll
        for (int nt = 0; nt < 4; nt++) {
            int c = wn * 32 + nt * 8 + 2 * lq;
            float ba = __ldg(b1 + c), bb = __ldg(b1 + c + 1);
            float2 v0, v1;
            v0.x = fmaxf(acc[mt][nt][0] + ba, 0.f);
            v0.y = fmaxf(acc[mt][nt][1] + bb, 0.f);
            v1.x = fmaxf(acc[mt][nt][2] + ba, 0.f);
            v1.y = fmaxf(acc[mt][nt][3] + bb, 0.f);
            *(float2*)(As + r0 * SLDK + c)       = v0;
            *(float2*)(As + (r0 + 8) * SLDK + c) = v1;
            acc[mt][nt][0] = 0.f; acc[mt][nt][1] = 0.f;
            acc[mt][nt][2] = 0.f; acc[mt][nt][3] = 0.f;
        }
    }
    // Load W2 into Bs
    #pragma unroll
    for (int r = 0; r < 16; r++) {
        int idx = t + r * 256;
        int k   = idx >> 5;
        int c4  = (idx & 31) * 4;
        *(float4*)(Bs + k * SLDB + c4) = *(const float4*)(W2 + k * F + c4);
    }
    __syncthreads();

    // ---- stage 2: H = relu(T @ W2 + b2) ----
    #pragma unroll 4
    for (int ks = 0; ks < 128; ks += 8) {
        uint32_t ahi[2][4], alo[2][4], bhi[4][2], blo[4][2];
        #pragma unroll
        for (int mt = 0; mt < 2; mt++) {
            int mb = wm * 32 + mt * 16 + lg;
            const float* ap = As + mb * SLDK + ks + lq;
            split_tf32(ap[0],            ahi[mt][0], alo[mt][0]);
            split_tf32(ap[8 * SLDK],     ahi[mt][1], alo[mt][1]);
            split_tf32(ap[4],            ahi[mt][2], alo[mt][2]);
            split_tf32(ap[8 * SLDK + 4], ahi[mt][3], alo[mt][3]);
        }
        #pragma unroll
        for (int nt = 0; nt < 4; nt++) {
            int nb = wn * 32 + nt * 8 + lg;
            const float* bp = Bs + (ks + lq) * SLDB + nb;
            split_tf32(bp[0],        bhi[nt][0], blo[nt][0]);
            split_tf32(bp[4 * SLDB], bhi[nt][1], blo[nt][1]);
        }
        #pragma unroll
        for (int mt = 0; mt < 2; mt++)
            #pragma unroll
            for (int nt = 0; nt < 4; nt++) {
                mma_tf32(acc[mt][nt], ahi[mt], bhi[nt]);
                mma_tf32(acc[mt][nt], ahi[mt], blo[nt]);
                mma_tf32(acc[mt][nt], alo[mt], bhi[nt]);
            }
    }

    if (!FUSE_CLS) {
        // epilogue 2: write H to gmem
        #pragma unroll
        for (int mt = 0; mt < 2; mt++) {
            int r0 = m0 + wm * 32 + mt * 16 + lg;
            #pragma unroll
            for (int nt = 0; nt < 4; nt++) {
                int c = wn * 32 + nt * 8 + 2 * lq;
                float ba = __ldg(b2 + c), bb = __ldg(b2 + c + 1);
                if (r0 < n) {
                    float2 v;
                    v.x = fmaxf(acc[mt][nt][0] + ba, 0.f);
                    v.y = fmaxf(acc[mt][nt][1] + bb, 0.f);
                    *(float2*)(Out + (size_t)r0 * F + c) = v;
                }
                if (r0 + 8 < n) {
                    float2 v;
                    v.x = fmaxf(acc[mt][nt][2] + ba, 0.f);
                    v.y = fmaxf(acc[mt][nt][3] + bb, 0.f);
                    *(float2*)(Out + (size_t)(r0 + 8) * F + c) = v;
                }
            }
        }
    } else {
        // epilogue 2 (fused): H -> As[m][k], then classifier + log_softmax in-block
        __syncthreads();   // all warps done reading As (T)
        #pragma unroll
        for (int mt = 0; mt < 2; mt++) {
            int r0 = wm * 32 + mt * 16 + lg;
            #pragma unroll
            for (int nt = 0; nt < 4; nt++) {
                int c = wn * 32 + nt * 8 + 2 * lq;
                float ba = __ldg(b2 + c), bb = __ldg(b2 + c + 1);
                float2 v0, v1;
                v0.x = fmaxf(acc[mt][nt][0] + ba, 0.f);
                v0.y = fmaxf(acc[mt][nt][1] + bb, 0.f);
                v1.x = fmaxf(acc[mt][nt][2] + ba, 0.f);
                v1.y = fmaxf(acc[mt][nt][3] + bb, 0.f);
                *(float2*)(As + r0 * SLDK + c)       = v0;
                *(float2*)(As + (r0 + 8) * SLDK + c) = v1;
            }
        }
        // stage Wl (compact 128x40), bl into the dead Bs region
        float* Ws  = Bs;
        float* Ls  = Bs + 6144;
        float* bls = Bs + 9088;
        #pragma unroll
        for (int r = 0; r < 5; r++) {
            int idx = t + r * 256;
            ((float4*)Ws)[idx] = ((const float4*)Wl)[idx];
        }
        if (t < NCLS) bls[t] = bl[t];
        __syncthreads();

        if (wid < 4) {
            const int mb = wid * 16;
            float a5[5][4];
            #pragma unroll
            for (int j = 0; j < 5; j++)
                #pragma unroll
                for (int c = 0; c < 4; c++) a5[j][c] = 0.f;

            #pragma unroll 4
            for (int ks = 0; ks < 128; ks += 8) {
                uint32_t ahi[4], alo[4], bhi[5][2], blo[5][2];
                const float* ap = As + (mb + lg) * SLDK + ks + lq;
                split_tf32(ap[0],            ahi[0], alo[0]);
                split_tf32(ap[8 * SLDK],     ahi[1], alo[1]);
                split_tf32(ap[4],            ahi[2], alo[2]);
                split_tf32(ap[8 * SLDK + 4], ahi[3], alo[3]);
                #pragma unroll
                for (int nt = 0; nt < 5; nt++) {
                    const float* bp = Ws + (ks + lq) * NCLS + nt * 8 + lg;
                    split_tf32(bp[0],        bhi[nt][0], blo[nt][0]);
                    split_tf32(bp[4 * NCLS], bhi[nt][1], blo[nt][1]);
                }
                #pragma unroll
                for (int nt = 0; nt < 5; nt++) {
                    mma_tf32(a5[nt], ahi, bhi[nt]);
                    mma_tf32(a5[nt], ahi, blo[nt]);
                    mma_tf32(a5[nt], alo, bhi[nt]);
                }
            }
            #pragma unroll
            for (int nt = 0; nt < 5; nt++) {
                int c = nt * 8 + 2 * lq;
                float ba = bls[c], bb = bls[c + 1];
                Ls[(mb + lg) * LSLD + c]         = a5[nt][0] + ba;
                Ls[(mb + lg) * LSLD + c + 1]     = a5[nt][1] + bb;
                Ls[(mb + lg + 8) * LSLD + c]     = a5[nt][2] + ba;
                Ls[(mb + lg + 8) * LSLD + c + 1] = a5[nt][3] + bb;
            }
        }
        __syncthreads();

        if (t < 64 && m0 + t < n) {
            const float* row = Ls + t * LSLD;
            float vmax = row[0];
            #pragma unroll
            for (int i = 1; i < NCLS; i++) vmax = fmaxf(vmax, row[i]);
            float es = 0.f;
            #pragma unroll
            for (int i = 0; i < NCLS; i++) es += __expf(row[i] - vmax);
            float lse = vmax + __logf(es);
            float* op = cls_out + (size_t)(m0 + t) * NCLS;
            #pragma unroll
            for (int i = 0; i < NCLS; i++) op[i] = row[i] - lse;
        }
    }
}

// ---------------- host launch ----------------
extern "C" void kernel_launch(void* const* d_in, const int* in_sizes, int n_in,
                              void* d_out, int out_size)
{
    const float* x         = (const float*)d_in[0];
    const void*  edge_idx  = d_in[1];
    const float* edge_attr = (const float*)d_in[2];
    const float* eps1 = (const float*)d_in[3];
    const float* We1  = (const float*)d_in[4];
    const float* be1  = (const float*)d_in[5];
    const float* W11  = (const float*)d_in[6];
    const float* b11  = (const float*)d_in[7];
    const float* W12  = (const float*)d_in[8];
    const float* b12  = (const float*)d_in[9];
    const float* eps2 = (const float*)d_in[10];
    const float* We2  = (const float*)d_in[11];
    const float* be2  = (const float*)d_in[12];
    const float* W21  = (const float*)d_in[13];
    const float* b21  = (const float*)d_in[14];
    const float* W22  = (const float*)d_in[15];
    const float* b22  = (const float*)d_in[16];
    const float* Wl   = (const float*)d_in[17];
    const float* bl   = (const float*)d_in[18];
    float* out = (float*)d_out;

    const int N = in_sizes[0] / F;
    const int E = in_sizes[2];

    static float *buf_b = nullptr;
    if (!buf_b) {
        cudaGetSymbolAddress((void**)&buf_b, g_buf_b);
        cudaFuncSetAttribute(gine_kernel<false>, cudaFuncAttributeMaxDynamicSharedMemorySize, SMEM_MLP);
        cudaFuncSetAttribute(gine_kernel<true>,  cudaFuncAttributeMaxDynamicSharedMemorySize, SMEM_MLP);
    }

    const int TB = 256;
    int ebl = (E + TB - 1) / TB;
    int nbl = (N + TB) / TB;
    int mbl = (N + TM - 1) / TM;
    int sbl = (N + 1 + 1023) / 1024;   // scan blocks (<= NSB)

    // CSR build
    detect_kernel<<<1, 256>>>((const unsigned int*)edge_idx);
    zero_counts_kernel<<<nbl, TB>>>(N);
    extract_hist_kernel<<<ebl, TB>>>(edge_idx, E);
    scan_sums_kernel<<<sbl, 1024>>>(N);
    scan_blocks_kernel<<<1, NSB>>>(sbl);
    scan_apply_kernel<<<sbl, 1024>>>(N);
    scatter_kernel<<<ebl, TB>>>(edge_attr, E);

    // conv1: agg + MLP fused
    gine_kernel<false><<<mbl, TB, SMEM_MLP>>>(
        (const float4*)x, We1, be1, eps1, W11, b11, W12, b12, buf_b, N,
        nullptr, nullptr, nullptr);
    // conv2: agg + MLP + classifier + log_softmax fused
    gine_kernel<true><<<mbl, TB, SMEM_MLP>>>(
        (const float4*)buf_b, We2, be2, eps2, W21, b21, W22, b22, nullptr, N,
        Wl, bl, out);
}

// round 12
// speedup vs baseline: 1.2327x; 1.2327x over previous
#include <cuda_runtime.h>
#include <math_constants.h>
#include <stdint.h>

#define MAXN 100000
#define MAXE 1600000
#define F 128
#define F4 32
#define NCLS 40
#define NSB  128   // max scan blocks (MAXN/1024+1 = 99)

// ---------------- device scratch ----------------
__device__ int   g_is64;
__device__ int   g_src[MAXE];
__device__ int   g_dst[MAXE];
__device__ int2  g_perm[MAXE];     // .x = src node, .y = edge_attr bits
__device__ int   g_counts[MAXN + 1];
__device__ int   g_offsets[MAXN + 1];
__device__ int   g_cursor[MAXN];
__device__ unsigned long long g_scan_desc[NSB];  // lookback descriptor: value<<2 | state
__device__ float g_buf_a[(size_t)MAXN * F];
__device__ float g_buf_b[(size_t)MAXN * F];

// ---------------- init: zero counts + scan descriptors, detect dtype ----------------
__global__ void init_kernel(const unsigned int* __restrict__ ei, int n) {
    int i = blockIdx.x * blockDim.x + threadIdx.x;
    if (i <= n) g_counts[i] = 0;
    if (i < NSB) g_scan_desc[i] = 0ULL;
    if (blockIdx.x == 0) {
        __shared__ int any_nonzero;
        if (threadIdx.x == 0) any_nonzero = 0;
        __syncthreads();
        for (int k = threadIdx.x; k < 1024; k += blockDim.x)
            if (ei[2 * k + 1] != 0u) any_nonzero = 1;
        __syncthreads();
        if (threadIdx.x == 0) g_is64 = (any_nonzero == 0) ? 1 : 0;
    }
}

// extract + histogram in one pass over E
__global__ void extract_hist_kernel(const void* __restrict__ ei, int E) {
    int e = blockIdx.x * blockDim.x + threadIdx.x;
    if (e >= E) return;
    int s, d;
    if (g_is64) {
        const long long* p = (const long long*)ei;
        s = (int)p[e];
        d = (int)p[(size_t)E + e];
    } else {
        const int* p = (const int*)ei;
        s = p[e];
        d = p[E + e];
    }
    g_src[e] = s;
    g_dst[e] = d;
    atomicAdd(&g_counts[d], 1);
}

// ---------------- single-pass decoupled-lookback scan over counts[0..n] ----------------
// grid <= 99 blocks -> all resident on 148 SMs, spin-wait is safe.
__global__ void __launch_bounds__(1024) scan_lookback_kernel(int n) {
    __shared__ int wsum[32];
    __shared__ int s_prefix;
    int lane = threadIdx.x & 31;
    int wid  = threadIdx.x >> 5;
    int bid  = blockIdx.x;
    int i = bid * 1024 + threadIdx.x;
    int v = (i <= n) ? g_counts[i] : 0;

    // block-wide inclusive scan
    int x = v;
    #pragma unroll
    for (int o = 1; o < 32; o <<= 1) {
        int y = __shfl_up_sync(0xffffffffu, x, o);
        if (lane >= o) x += y;
    }
    if (lane == 31) wsum[wid] = x;
    __syncthreads();
    if (wid == 0) {
        int s = wsum[lane];
        #pragma unroll
        for (int o = 1; o < 32; o <<= 1) {
            int y = __shfl_up_sync(0xffffffffu, s, o);
            if (lane >= o) s += y;
        }
        wsum[lane] = s;
    }
    __syncthreads();
    int incl   = x + (wid > 0 ? wsum[wid - 1] : 0);
    int btotal = wsum[31];

    if (threadIdx.x == 0) {
        s_prefix = 0;
        if (bid == 0) {
            atomicExch(&g_scan_desc[0], (((unsigned long long)btotal) << 2) | 2ULL);
        } else {
            atomicExch(&g_scan_desc[bid], (((unsigned long long)btotal) << 2) | 1ULL);
            int prefix = 0;
            int j = bid - 1;
            while (true) {
                unsigned long long d;
                do { d = atomicAdd(&g_scan_desc[j], 0ULL); } while ((d & 3ULL) == 0ULL);
                prefix += (int)(d >> 2);
                if ((d & 3ULL) == 2ULL) break;
                j--;
            }
            atomicExch(&g_scan_desc[bid],
                       (((unsigned long long)(prefix + btotal)) << 2) | 2ULL);
            s_prefix = prefix;
        }
    }
    __syncthreads();

    int excl = s_prefix + incl - v;
    if (i <= n) {
        g_offsets[i] = excl;
        if (i < n) g_cursor[i] = excl;
    }
}

__global__ void scatter_kernel(const float* __restrict__ edge_attr, int E) {
    int e = blockIdx.x * blockDim.x + threadIdx.x;
    if (e >= E) return;
    int d = g_dst[e];
    int pos = atomicAdd(&g_cursor[d], 1);
    g_perm[pos] = make_int2(g_src[e], __float_as_int(edge_attr[e]));
}

// ---------------- GINE aggregation: warp per node, unroll-4 for MLP ----------------
__global__ void __launch_bounds__(256) agg_kernel(
    const float4* __restrict__ xin, const float* __restrict__ We,
    const float* __restrict__ be, const float* __restrict__ eps_p,
    float4* __restrict__ out, int n)
{
    int warp = (blockIdx.x * blockDim.x + threadIdx.x) >> 5;
    int lane = threadIdx.x & 31;
    if (warp >= n) return;

    float4 w  = ((const float4*)We)[lane];
    float4 bb = ((const float4*)be)[lane];
    int beg = g_offsets[warp];
    int end = g_offsets[warp + 1];

    float4 acc = make_float4(0.f, 0.f, 0.f, 0.f);
    int p = beg;
    for (; p + 3 < end; p += 4) {
        int2 pe0 = g_perm[p];
        int2 pe1 = g_perm[p + 1];
        int2 pe2 = g_perm[p + 2];
        int2 pe3 = g_perm[p + 3];
        float4 x0 = __ldg(&xin[(size_t)pe0.x * F4 + lane]);
        float4 x1 = __ldg(&xin[(size_t)pe1.x * F4 + lane]);
        float4 x2 = __ldg(&xin[(size_t)pe2.x * F4 + lane]);
        float4 x3 = __ldg(&xin[(size_t)pe3.x * F4 + lane]);
        float e0 = __int_as_float(pe0.y);
        float e1 = __int_as_float(pe1.y);
        float e2 = __int_as_float(pe2.y);
        float e3 = __int_as_float(pe3.y);
        acc.x += fmaxf(fmaf(e0, w.x, x0.x) + bb.x, 0.f);
        acc.y += fmaxf(fmaf(e0, w.y, x0.y) + bb.y, 0.f);
        acc.z += fmaxf(fmaf(e0, w.z, x0.z) + bb.z, 0.f);
        acc.w += fmaxf(fmaf(e0, w.w, x0.w) + bb.w, 0.f);
        acc.x += fmaxf(fmaf(e1, w.x, x1.x) + bb.x, 0.f);
        acc.y += fmaxf(fmaf(e1, w.y, x1.y) + bb.y, 0.f);
        acc.z += fmaxf(fmaf(e1, w.z, x1.z) + bb.z, 0.f);
        acc.w += fmaxf(fmaf(e1, w.w, x1.w) + bb.w, 0.f);
        acc.x += fmaxf(fmaf(e2, w.x, x2.x) + bb.x, 0.f);
        acc.y += fmaxf(fmaf(e2, w.y, x2.y) + bb.y, 0.f);
        acc.z += fmaxf(fmaf(e2, w.z, x2.z) + bb.z, 0.f);
        acc.w += fmaxf(fmaf(e2, w.w, x2.w) + bb.w, 0.f);
        acc.x += fmaxf(fmaf(e3, w.x, x3.x) + bb.x, 0.f);
        acc.y += fmaxf(fmaf(e3, w.y, x3.y) + bb.y, 0.f);
        acc.z += fmaxf(fmaf(e3, w.z, x3.z) + bb.z, 0.f);
        acc.w += fmaxf(fmaf(e3, w.w, x3.w) + bb.w, 0.f);
    }
    for (; p < end; p++) {
        int2 pe = g_perm[p];
        float4 xj = __ldg(&xin[(size_t)pe.x * F4 + lane]);
        float ea = __int_as_float(pe.y);
        acc.x += fmaxf(fmaf(ea, w.x, xj.x) + bb.x, 0.f);
        acc.y += fmaxf(fmaf(ea, w.y, xj.y) + bb.y, 0.f);
        acc.z += fmaxf(fmaf(ea, w.z, xj.z) + bb.z, 0.f);
        acc.w += fmaxf(fmaf(ea, w.w, xj.w) + bb.w, 0.f);
    }
    float epv = 1.f + __ldg(eps_p);
    float4 xi = __ldg(&xin[(size_t)warp * F4 + lane]);
    float4 r;
    r.x = fmaf(epv, xi.x, acc.x);
    r.y = fmaf(epv, xi.y, acc.y);
    r.z = fmaf(epv, xi.z, acc.z);
    r.w = fmaf(epv, xi.w, acc.w);
    out[(size_t)warp * F4 + lane] = r;
}

// ---------------- tf32 helpers ----------------
__device__ __forceinline__ uint32_t f2tf32(float x) {
    uint32_t r;
    asm("cvt.rna.tf32.f32 %0, %1;" : "=r"(r) : "f"(x));
    return r;
}
__device__ __forceinline__ void split_tf32(float x, uint32_t& hi, uint32_t& lo) {
    hi = f2tf32(x);
    lo = f2tf32(x - __uint_as_float(hi));
}
__device__ __forceinline__ void mma_tf32(float* d, const uint32_t* a, const uint32_t* b) {
    asm volatile(
        "mma.sync.aligned.m16n8k8.row.col.f32.tf32.tf32.f32 "
        "{%0,%1,%2,%3}, {%4,%5,%6,%7}, {%8,%9}, {%0,%1,%2,%3};"
        : "+f"(d[0]), "+f"(d[1]), "+f"(d[2]), "+f"(d[3])
        : "r"(a[0]), "r"(a[1]), "r"(a[2]), "r"(a[3]), "r"(b[0]), "r"(b[1]));
}

// ---------------- tf32 tensor-core fused MLP (+ optional fused classifier) ----------------
#define TM   64
#define SLDK 132   // As[m][k] row stride (conflict-free)
#define SLDB 136   // Bs[k][n] row stride
#define LSLD 44
#define SMEM_MLP ((TM * SLDK + 128 * SLDB) * 4)

template <bool FUSE_CLS>
__global__ void __launch_bounds__(256, 2) mlp_kernel(
    const float* __restrict__ In,
    const float* __restrict__ W1, const float* __restrict__ b1,
    const float* __restrict__ W2, const float* __restrict__ b2,
    float* __restrict__ Out, int n,
    const float* __restrict__ Wl, const float* __restrict__ bl,
    float* __restrict__ cls_out)
{
    extern __shared__ float sm[];
    float* As = sm;                // [TM m][128 k] row-major
    float* Bs = sm + TM * SLDK;    // [128 k][128 n]

    const int t    = threadIdx.x;
    const int lane = t & 31;
    const int wid  = t >> 5;
    const int wm   = wid & 1;
    const int wn   = wid >> 1;
    const int m0   = blockIdx.x * TM;
    const int lq   = lane & 3;
    const int lg   = lane >> 2;

    // Load In tile row-major
    #pragma unroll
    for (int r = 0; r < 8; r++) {
        int idx = t + r * 256;
        int m   = idx >> 5;
        int k4  = (idx & 31) * 4;
        float4 v = make_float4(0.f, 0.f, 0.f, 0.f);
        if (m0 + m < n) v = *(const float4*)(In + (size_t)(m0 + m) * F + k4);
        *(float4*)(As + m * SLDK + k4) = v;
    }
    // Load W1 into Bs
    #pragma unroll
    for (int r = 0; r < 16; r++) {
        int idx = t + r * 256;
        int k   = idx >> 5;
        int c4  = (idx & 31) * 4;
        *(float4*)(Bs + k * SLDB + c4) = *(const float4*)(W1 + k * F + c4);
    }
    __syncthreads();

    float acc[2][4][4];
    #pragma unroll
    for (int i = 0; i < 2; i++)
        #pragma unroll
        for (int j = 0; j < 4; j++)
            #pragma unroll
            for (int c = 0; c < 4; c++) acc[i][j][c] = 0.f;

    // ---- stage 1: T = In @ W1 ----
    #pragma unroll 4
    for (int ks = 0; ks < 128; ks += 8) {
        uint32_t ahi[2][4], alo[2][4], bhi[4][2], blo[4][2];
        #pragma unroll
        for (int mt = 0; mt < 2; mt++) {
            int mb = wm * 32 + mt * 16 + lg;
            const float* ap = As + mb * SLDK + ks + lq;
            split_tf32(ap[0],            ahi[mt][0], alo[mt][0]);
            split_tf32(ap[8 * SLDK],     ahi[mt][1], alo[mt][1]);
            split_tf32(ap[4],            ahi[mt][2], alo[mt][2]);
            split_tf32(ap[8 * SLDK + 4], ahi[mt][3], alo[mt][3]);
        }
        #pragma unroll
        for (int nt = 0; nt < 4; nt++) {
            int nb = wn * 32 + nt * 8 + lg;
            const float* bp = Bs + (ks + lq) * SLDB + nb;
            split_tf32(bp[0],        bhi[nt][0], blo[nt][0]);
            split_tf32(bp[4 * SLDB], bhi[nt][1], blo[nt][1]);
        }
        #pragma unroll
        for (int mt = 0; mt < 2; mt++)
            #pragma unroll
            for (int nt = 0; nt < 4; nt++) {
                mma_tf32(acc[mt][nt], ahi[mt], bhi[nt]);
                mma_tf32(acc[mt][nt], ahi[mt], blo[nt]);
                mma_tf32(acc[mt][nt], alo[mt], bhi[nt]);
            }
    }
    __syncthreads();

    // epilogue 1: T = relu(acc + b1) stored into As[m][hidden]
    #pragma unroll
    for (int mt = 0; mt < 2; mt++) {
        int r0 = wm * 32 + mt * 16 + lg;
        #pragma unroll
        for (int nt = 0; nt < 4; nt++) {
            int c = wn * 32 + nt * 8 + 2 * lq;
            float ba = __ldg(b1 + c), bb = __ldg(b1 + c + 1);
            float2 v0, v1;
            v0.x = fmaxf(acc[mt][nt][0] + ba, 0.f);
            v0.y = fmaxf(acc[mt][nt][1] + bb, 0.f);
            v1.x = fmaxf(acc[mt][nt][2] + ba, 0.f);
            v1.y = fmaxf(acc[mt][nt][3] + bb, 0.f);
            *(float2*)(As + r0 * SLDK + c)       = v0;
            *(float2*)(As + (r0 + 8) * SLDK + c) = v1;
            acc[mt][nt][0] = 0.f; acc[mt][nt][1] = 0.f;
            acc[mt][nt][2] = 0.f; acc[mt][nt][3] = 0.f;
        }
    }
    // Load W2 into Bs
    #pragma unroll
    for (int r = 0; r < 16; r++) {
        int idx = t + r * 256;
        int k   = idx >> 5;
        int c4  = (idx & 31) * 4;
        *(float4*)(Bs + k * SLDB + c4) = *(const float4*)(W2 + k * F + c4);
    }
    __syncthreads();

    // ---- stage 2: H = relu(T @ W2 + b2) ----
    #pragma unroll 4
    for (int ks = 0; ks < 128; ks += 8) {
        uint32_t ahi[2][4], alo[2][4], bhi[4][2], blo[4][2];
        #pragma unroll
        for (int mt = 0; mt < 2; mt++) {
            int mb = wm * 32 + mt * 16 + lg;
            const float* ap = As + mb * SLDK + ks + lq;
            split_tf32(ap[0],            ahi[mt][0], alo[mt][0]);
            split_tf32(ap[8 * SLDK],     ahi[mt][1], alo[mt][1]);
            split_tf32(ap[4],            ahi[mt][2], alo[mt][2]);
            split_tf32(ap[8 * SLDK + 4], ahi[mt][3], alo[mt][3]);
        }
        #pragma unroll
        for (int nt = 0; nt < 4; nt++) {
            int nb = wn * 32 + nt * 8 + lg;
            const float* bp = Bs + (ks + lq) * SLDB + nb;
            split_tf32(bp[0],        bhi[nt][0], blo[nt][0]);
            split_tf32(bp[4 * SLDB], bhi[nt][1], blo[nt][1]);
        }
        #pragma unroll
        for (int mt = 0; mt < 2; mt++)
            #pragma unroll
            for (int nt = 0; nt < 4; nt++) {
                mma_tf32(acc[mt][nt], ahi[mt], bhi[nt]);
                mma_tf32(acc[mt][nt], ahi[mt], blo[nt]);
                mma_tf32(acc[mt][nt], alo[mt], bhi[nt]);
            }
    }

    if (!FUSE_CLS) {
        // epilogue 2: write H to gmem
        #pragma unroll
        for (int mt = 0; mt < 2; mt++) {
            int r0 = m0 + wm * 32 + mt * 16 + lg;
            #pragma unroll
            for (int nt = 0; nt < 4; nt++) {
                int c = wn * 32 + nt * 8 + 2 * lq;
                float ba = __ldg(b2 + c), bb = __ldg(b2 + c + 1);
                if (r0 < n) {
                    float2 v;
                    v.x = fmaxf(acc[mt][nt][0] + ba, 0.f);
                    v.y = fmaxf(acc[mt][nt][1] + bb, 0.f);
                    *(float2*)(Out + (size_t)r0 * F + c) = v;
                }
                if (r0 + 8 < n) {
                    float2 v;
                    v.x = fmaxf(acc[mt][nt][2] + ba, 0.f);
                    v.y = fmaxf(acc[mt][nt][3] + bb, 0.f);
                    *(float2*)(Out + (size_t)(r0 + 8) * F + c) = v;
                }
            }
        }
    } else {
        // epilogue 2 (fused): H -> As[m][k], then classifier + log_softmax in-block
        __syncthreads();   // all warps done reading As (T)
        #pragma unroll
        for (int mt = 0; mt < 2; mt++) {
            int r0 = wm * 32 + mt * 16 + lg;
            #pragma unroll
            for (int nt = 0; nt < 4; nt++) {
                int c = wn * 32 + nt * 8 + 2 * lq;
                float ba = __ldg(b2 + c), bb = __ldg(b2 + c + 1);
                float2 v0, v1;
                v0.x = fmaxf(acc[mt][nt][0] + ba, 0.f);
                v0.y = fmaxf(acc[mt][nt][1] + bb, 0.f);
                v1.x = fmaxf(acc[mt][nt][2] + ba, 0.f);
                v1.y = fmaxf(acc[mt][nt][3] + bb, 0.f);
                *(float2*)(As + r0 * SLDK + c)       = v0;
                *(float2*)(As + (r0 + 8) * SLDK + c) = v1;
            }
        }
        // stage Wl (compact 128x40), bl into the dead Bs region
        float* Ws  = Bs;
        float* Ls  = Bs + 6144;
        float* bls = Bs + 9088;
        #pragma unroll
        for (int r = 0; r < 5; r++) {
            int idx = t + r * 256;
            ((float4*)Ws)[idx] = ((const float4*)Wl)[idx];
        }
        if (t < NCLS) bls[t] = bl[t];
        __syncthreads();

        if (wid < 4) {
            const int mb = wid * 16;
            float a5[5][4];
            #pragma unroll
            for (int j = 0; j < 5; j++)
                #pragma unroll
                for (int c = 0; c < 4; c++) a5[j][c] = 0.f;

            #pragma unroll 4
            for (int ks = 0; ks < 128; ks += 8) {
                uint32_t ahi[4], alo[4], bhi[5][2], blo[5][2];
                const float* ap = As + (mb + lg) * SLDK + ks + lq;
                split_tf32(ap[0],            ahi[0], alo[0]);
                split_tf32(ap[8 * SLDK],     ahi[1], alo[1]);
                split_tf32(ap[4],            ahi[2], alo[2]);
                split_tf32(ap[8 * SLDK + 4], ahi[3], alo[3]);
                #pragma unroll
                for (int nt = 0; nt < 5; nt++) {
                    const float* bp = Ws + (ks + lq) * NCLS + nt * 8 + lg;
                    split_tf32(bp[0],        bhi[nt][0], blo[nt][0]);
                    split_tf32(bp[4 * NCLS], bhi[nt][1], blo[nt][1]);
                }
                #pragma unroll
                for (int nt = 0; nt < 5; nt++) {
                    mma_tf32(a5[nt], ahi, bhi[nt]);
                    mma_tf32(a5[nt], ahi, blo[nt]);
                    mma_tf32(a5[nt], alo, bhi[nt]);
                }
            }
            #pragma unroll
            for (int nt = 0; nt < 5; nt++) {
                int c = nt * 8 + 2 * lq;
                float ba = bls[c], bb = bls[c + 1];
                Ls[(mb + lg) * LSLD + c]         = a5[nt][0] + ba;
                Ls[(mb + lg) * LSLD + c + 1]     = a5[nt][1] + bb;
                Ls[(mb + lg + 8) * LSLD + c]     = a5[nt][2] + ba;
                Ls[(mb + lg + 8) * LSLD + c + 1] = a5[nt][3] + bb;
            }
        }
        __syncthreads();

        if (t < 64 && m0 + t < n) {
            const float* row = Ls + t * LSLD;
            float vmax = row[0];
            #pragma unroll
            for (int i = 1; i < NCLS; i++) vmax = fmaxf(vmax, row[i]);
            float es = 0.f;
            #pragma unroll
            for (int i = 0; i < NCLS; i++) es += __expf(row[i] - vmax);
            float lse = vmax + __logf(es);
            float* op = cls_out + (size_t)(m0 + t) * NCLS;
            #pragma unroll
            for (int i = 0; i < NCLS; i++) op[i] = row[i] - lse;
        }
    }
}

// ---------------- host launch ----------------
extern "C" void kernel_launch(void* const* d_in, const int* in_sizes, int n_in,
                              void* d_out, int out_size)
{
    const float* x         = (const float*)d_in[0];
    const void*  edge_idx  = d_in[1];
    const float* edge_attr = (const float*)d_in[2];
    const float* eps1 = (const float*)d_in[3];
    const float* We1  = (const float*)d_in[4];
    const float* be1  = (const float*)d_in[5];
    const float* W11  = (const float*)d_in[6];
    const float* b11  = (const float*)d_in[7];
    const float* W12  = (const float*)d_in[8];
    const float* b12  = (const float*)d_in[9];
    const float* eps2 = (const float*)d_in[10];
    const float* We2  = (const float*)d_in[11];
    const float* be2  = (const float*)d_in[12];
    const float* W21  = (const float*)d_in[13];
    const float* b21  = (const float*)d_in[14];
    const float* W22  = (const float*)d_in[15];
    const float* b22  = (const float*)d_in[16];
    const float* Wl   = (const float*)d_in[17];
    const float* bl   = (const float*)d_in[18];
    float* out = (float*)d_out;

    const int N = in_sizes[0] / F;
    const int E = in_sizes[2];

    static float *buf_a = nullptr, *buf_b = nullptr;
    if (!buf_a) {
        cudaGetSymbolAddress((void**)&buf_a, g_buf_a);
        cudaGetSymbolAddress((void**)&buf_b, g_buf_b);
        cudaFuncSetAttribute(mlp_kernel<false>, cudaFuncAttributeMaxDynamicSharedMemorySize, SMEM_MLP);
        cudaFuncSetAttribute(mlp_kernel<true>,  cudaFuncAttributeMaxDynamicSharedMemorySize, SMEM_MLP);
    }

    const int TB = 256;
    int ebl = (E + TB - 1) / TB;
    int nbl = (N + TB) / TB;
    int wbl = (N * 32 + TB - 1) / TB;
    int mbl = (N + TM - 1) / TM;
    int sbl = (N + 1 + 1023) / 1024;   // scan blocks (<= NSB, all resident)

    // CSR build: init(1), extract_hist(2), scan(3), scatter(4) <- ncu slot
    init_kernel<<<nbl, TB>>>((const unsigned int*)edge_idx, N);
    extract_hist_kernel<<<ebl, TB>>>(edge_idx, E);
    scan_lookback_kernel<<<sbl, 1024>>>(N);
    scatter_kernel<<<ebl, TB>>>(edge_attr, E);

    // conv1
    agg_kernel<<<wbl, TB>>>((const float4*)x, We1, be1, eps1, (float4*)buf_a, N);
    mlp_kernel<false><<<mbl, TB, SMEM_MLP>>>(buf_a, W11, b11, W12, b12, buf_b, N,
                                             nullptr, nullptr, nullptr);
    // conv2 + fused classifier/log_softmax
    agg_kernel<<<wbl, TB>>>((const float4*)buf_b, We2, be2, eps2, (float4*)buf_a, N);
    mlp_kernel<true><<<mbl, TB, SMEM_MLP>>>(buf_a, W21, b21, W22, b22, nullptr, N,
                                            Wl, bl, out);
}